// round 16
// baseline (speedup 1.0000x reference)
#include <cuda_runtime.h>
#include <cuda_bf16.h>
#include <cstdint>

#define BI 4
#define CI 64
#define HI 128
#define WI 128
#define HWI (HI*WI)
#define JO 18
#define JP 20
#define CO 64
#define KKN 9
#define TPX 128

typedef unsigned long long u64;

__device__ __forceinline__ void ffma2(u64 &d, u64 a, u64 b) {
    asm("fma.rn.f32x2 %0, %1, %2, %0;" : "+l"(d) : "l"(a), "l"(b));
}
__device__ __forceinline__ u64 pack2(float lo, float hi) {
    u64 r; asm("mov.b64 %0, {%1, %2};" : "=l"(r) : "f"(lo), "f"(hi)); return r;
}
__device__ __forceinline__ float2 unpack2(u64 v) {
    float2 r; asm("mov.b64 {%0, %1}, %2;" : "=f"(r.x), "=f"(r.y) : "l"(v)); return r;
}

// Scratch: offsets [b][j][h][w]; channel-QUAD packed x [b][c4][p] (float4);
// transposed def-weights [kk][c][o]
__device__ float g_off[BI*JO*HWI];
__device__ __align__(16) float4 g_x4[BI*(CI/4)*HWI];   // 16 MB
__device__ float g_wt[KKN*CI*CO];

// ---------------------------------------------------------------------------
// Prep A: pack x channel quads: g_x4[b][c4][p] = (x[4c4..4c4+3] at pixel p)
// ---------------------------------------------------------------------------
__global__ void pack_x_kernel(const float* __restrict__ x) {
    int i = blockIdx.x * blockDim.x + threadIdx.x;   // over BI*16*HWI
    if (i < BI*(CI/4)*HWI) {
        int p = i & (HWI-1); int rest = i >> 14;
        int c4 = rest & 15;  int b = rest >> 4;
        const float* src = x + ((size_t)(b*CI + 4*c4))*HWI + p;
        g_x4[i] = make_float4(src[0], src[HWI], src[2*HWI], src[3*HWI]);
    }
}

// ---------------------------------------------------------------------------
// Prep B: transpose w_def [o][c][kk] -> g_wt [kk][c][o]
// ---------------------------------------------------------------------------
__global__ void transpose_wdef_kernel(const float* __restrict__ w_def) {
    int i = blockIdx.x * blockDim.x + threadIdx.x;
    if (i < KKN*CI*CO) {
        int o = i & 63; int rest = i >> 6; int c = rest % CI; int kk = rest / CI;
        g_wt[i] = w_def[(o*CI + c)*KKN + kk];
    }
}

// ---------------------------------------------------------------------------
// Kernel 1: offset conv, 1 pixel/thread, packed f32x2 accumulators.
// NOW reads channel-quad packed g_x4: 144 LDG.128 per thread (was 576 LDG.32).
// ---------------------------------------------------------------------------
__global__ __launch_bounds__(256, 4)
void offset_conv_kernel(const float* __restrict__ w_off,
                        const float* __restrict__ b_off) {
    __shared__ __align__(16) float ws[KKN*CI*JP];
    int tid = threadIdx.x;
    for (int i = tid; i < KKN*CI*JO; i += blockDim.x) {
        int j = i % JO; int rest = i / JO; int c = rest % CI; int tap = rest / CI;
        ws[(tap*CI + c)*JP + j] = w_off[(j*CI + c)*KKN + tap];
    }
    __syncthreads();

    int p = blockIdx.x * blockDim.x + tid;
    int b = p >> 14, rem = p & (HWI-1);
    int h = rem >> 7, w = rem & (WI-1);
    const float4* xb4 = g_x4 + (size_t)b*(CI/4)*HWI;

    u64 acc[9];
    #pragma unroll
    for (int q = 0; q < 9; q++)
        acc[q] = pack2(__ldg(&b_off[2*q]), __ldg(&b_off[2*q+1]));

    for (int tap = 0; tap < KKN; tap++) {
        int ky = tap / 3, kx = tap % 3;
        int y = h - 1 + ky, xx = w - 1 + kx;
        bool v = (y >= 0) & (y < HI) & (xx >= 0) & (xx < WI);
        int idx = y*WI + xx;
        const float* wtap = ws + tap*CI*JP;
        #pragma unroll 2
        for (int c4 = 0; c4 < CI/4; c4++) {
            float4 qv = v ? __ldg(xb4 + (size_t)c4*HWI + idx)
                          : make_float4(0.f, 0.f, 0.f, 0.f);
            const float* qf = (const float*)&qv;
            #pragma unroll
            for (int u = 0; u < 4; u++) {
                u64 a2 = pack2(qf[u], qf[u]);
                const float* wrow = wtap + (4*c4 + u)*JP;
                const ulonglong2* w4 = (const ulonglong2*)wrow;
                #pragma unroll
                for (int q = 0; q < 4; q++) {
                    ulonglong2 wv = w4[q];
                    ffma2(acc[2*q+0], a2, wv.x);
                    ffma2(acc[2*q+1], a2, wv.y);
                }
                u64 w8 = *(const u64*)(wrow + 16);
                ffma2(acc[8], a2, w8);
            }
        }
    }
    #pragma unroll
    for (int q = 0; q < 9; q++) {
        float2 vv = unpack2(acc[q]);
        g_off[(b*JO + 2*q+0)*HWI + rem] = vv.x;
        g_off[(b*JO + 2*q+1)*HWI + rem] = vv.y;
    }
}

// ---------------------------------------------------------------------------
// Kernel 2: per-tap im2col + register-blocked GEMM (unchanged from R15 best).
// Block = 128 threads = one image row. S[c][128] in smem (32 KB).
// Sampling: channel-QUAD gathers (LDG.128 from g_x4) + paired ffma2 blend.
// Next-tap dy/dx prefetched during GEMM.
// GEMM: 8o x 8px FFMA2 tile; weights uniform LDG.128 from g_wt + pack2.
// ---------------------------------------------------------------------------
__global__ __launch_bounds__(128, 4)
void deform_main_kernel(float* __restrict__ out) {
    __shared__ __align__(16) float S[CI*TPX];   // 32 KB

    int tid = threadIdx.x;
    int blk = blockIdx.x;
    int b = blk >> 7;
    int h = blk & 127;
    int rowoff = h * WI;
    const float4* x4b = g_x4 + (size_t)b*(CI/4)*HWI;
    int w = tid;
    const float* offp = g_off + b*JO*HWI + rowoff + w;

    int o0 = (tid >> 4) * 8;   // 8 output channels
    int qb = tid & 15;         // quad base: px 4*qb + 64*j

    u64 acc[8][4];
    #pragma unroll
    for (int o = 0; o < 8; o++)
        #pragma unroll
        for (int q = 0; q < 4; q++) acc[o][q] = 0ULL;

    // prefetch tap 0 offsets
    float dy = __ldg(offp + 0*HWI);
    float dx = __ldg(offp + 1*HWI);

    for (int kk = 0; kk < KKN; kk++) {
        __syncthreads();   // previous GEMM done reading S

        // bilinear setup for own pixel (dy/dx prefetched)
        float py = (float)(h - 1 + kk / 3) + dy;
        float px = (float)(w - 1 + kk % 3) + dx;
        float y0f = floorf(py), x0f = floorf(px);
        float fy = py - y0f, fx = px - x0f;
        int y0 = (int)y0f, x0 = (int)x0f;
        int y1 = y0 + 1,   x1 = x0 + 1;
        float vy0 = (y0 >= 0 && y0 < HI) ? 1.f : 0.f;
        float vy1 = (y1 >= 0 && y1 < HI) ? 1.f : 0.f;
        float vx0 = (x0 >= 0 && x0 < WI) ? 1.f : 0.f;
        float vx1 = (x1 >= 0 && x1 < WI) ? 1.f : 0.f;
        float w00 = (1.f - fy) * (1.f - fx) * vy0 * vx0;
        float w01 = (1.f - fy) * fx         * vy0 * vx1;
        float w10 = fy         * (1.f - fx) * vy1 * vx0;
        float w11 = fy         * fx         * vy1 * vx1;
        int y0c = min(max(y0, 0), HI-1), y1c = min(max(y1, 0), HI-1);
        int x0c = min(max(x0, 0), WI-1), x1c = min(max(x1, 0), WI-1);
        int i00 = y0c*WI + x0c, i01 = y0c*WI + x1c;
        int i10 = y1c*WI + x0c, i11 = y1c*WI + x1c;

        u64 W00 = pack2(w00, w00), W01 = pack2(w01, w01);
        u64 W10 = pack2(w10, w10), W11 = pack2(w11, w11);

        // sample channel quads -> S[4c4+k][tid]
        #pragma unroll 2
        for (int c4 = 0; c4 < CI/4; c4++) {
            const float4* xp = x4b + (size_t)c4*HWI;
            ulonglong2 n00 = __ldg((const ulonglong2*)(xp + i00));
            ulonglong2 n01 = __ldg((const ulonglong2*)(xp + i01));
            ulonglong2 n10 = __ldg((const ulonglong2*)(xp + i10));
            ulonglong2 n11 = __ldg((const ulonglong2*)(xp + i11));
            u64 sLo = 0ULL, sHi = 0ULL;
            ffma2(sLo, W00, n00.x);  ffma2(sHi, W00, n00.y);
            ffma2(sLo, W01, n01.x);  ffma2(sHi, W01, n01.y);
            ffma2(sLo, W10, n10.x);  ffma2(sHi, W10, n10.y);
            ffma2(sLo, W11, n11.x);  ffma2(sHi, W11, n11.y);
            float2 a = unpack2(sLo), c = unpack2(sHi);
            S[(4*c4+0)*TPX + tid] = a.x;
            S[(4*c4+1)*TPX + tid] = a.y;
            S[(4*c4+2)*TPX + tid] = c.x;
            S[(4*c4+3)*TPX + tid] = c.y;
        }
        __syncthreads();

        // prefetch next tap's offsets (hidden under GEMM)
        if (kk + 1 < KKN) {
            dy = __ldg(offp + (2*kk + 2)*HWI);
            dx = __ldg(offp + (2*kk + 3)*HWI);
        }

        // GEMM: acc[8o][8px] += W[o][c] * S[c][px]
        const float* wk = g_wt + kk*CI*CO + o0;
        #pragma unroll 2
        for (int c = 0; c < CI; c++) {
            const float* wr = wk + (c << 6);
            float4 wa = __ldg((const float4*)(wr));
            float4 wb = __ldg((const float4*)(wr + 4));
            u64 w2[8];
            w2[0] = pack2(wa.x, wa.x); w2[1] = pack2(wa.y, wa.y);
            w2[2] = pack2(wa.z, wa.z); w2[3] = pack2(wa.w, wa.w);
            w2[4] = pack2(wb.x, wb.x); w2[5] = pack2(wb.y, wb.y);
            w2[6] = pack2(wb.z, wb.z); w2[7] = pack2(wb.w, wb.w);
            const float* srow = S + c*TPX + 4*qb;
            ulonglong2 sj0 = *(const ulonglong2*)(srow);
            ulonglong2 sj1 = *(const ulonglong2*)(srow + 64);
            #pragma unroll
            for (int o = 0; o < 8; o++) {
                ffma2(acc[o][0], sj0.x, w2[o]);
                ffma2(acc[o][1], sj0.y, w2[o]);
                ffma2(acc[o][2], sj1.x, w2[o]);
                ffma2(acc[o][3], sj1.y, w2[o]);
            }
        }
    }

    // write out: thread's px quads at 4*qb + 64*j
    #pragma unroll
    for (int o = 0; o < 8; o++) {
        float* orow = out + (b*CO + o0 + o)*HWI + rowoff;
        #pragma unroll
        for (int j = 0; j < 2; j++) {
            float2 v0 = unpack2(acc[o][2*j+0]);
            float2 v1 = unpack2(acc[o][2*j+1]);
            float4 v = make_float4(v0.x, v0.y, v1.x, v1.y);
            *(float4*)(orow + 4*qb + 64*j) = v;
        }
    }
}

// ---------------------------------------------------------------------------
// Launch
// Inputs: x (4*64*128*128), w_off (18*64*9), b_off (18), w_def (64*64*9)
// Output: (4, 64, 128, 128) fp32
// ---------------------------------------------------------------------------
extern "C" void kernel_launch(void* const* d_in, const int* in_sizes, int n_in,
                              void* d_out, int out_size) {
    const float* x     = (const float*)d_in[0];
    const float* w_off = (const float*)d_in[1];
    const float* b_off = (const float*)d_in[2];
    const float* w_def = (const float*)d_in[3];
    float* out = (float*)d_out;

    const int total_px = BI*HWI;  // 65536

    pack_x_kernel<<<(BI*(CI/4)*HWI + 255)/256, 256>>>(x);
    transpose_wdef_kernel<<<(KKN*CI*CO + 255)/256, 256>>>(w_def);
    offset_conv_kernel<<<total_px/256, 256>>>(w_off, b_off);
    deform_main_kernel<<<total_px/TPX, TPX>>>(out);
}

// round 17
// speedup vs baseline: 1.0183x; 1.0183x over previous
#include <cuda_runtime.h>
#include <cuda_bf16.h>
#include <cstdint>

#define BI 4
#define CI 64
#define HI 128
#define WI 128
#define HWI (HI*WI)
#define JO 18
#define JP 20
#define CO 64
#define KKN 9
#define TPX 128

typedef unsigned long long u64;

__device__ __forceinline__ void ffma2(u64 &d, u64 a, u64 b) {
    asm("fma.rn.f32x2 %0, %1, %2, %0;" : "+l"(d) : "l"(a), "l"(b));
}
__device__ __forceinline__ u64 pack2(float lo, float hi) {
    u64 r; asm("mov.b64 %0, {%1, %2};" : "=l"(r) : "f"(lo), "f"(hi)); return r;
}
__device__ __forceinline__ float2 unpack2(u64 v) {
    float2 r; asm("mov.b64 {%0, %1}, %2;" : "=f"(r.x), "=f"(r.y) : "l"(v)); return r;
}

// Scratch: offsets [b][j][h][w]; channel-QUAD packed x [b][c4][p] (float4);
// transposed def-weights [kk][c][o]
__device__ float g_off[BI*JO*HWI];
__device__ __align__(16) float4 g_x4[BI*(CI/4)*HWI];   // 16 MB
__device__ float g_wt[KKN*CI*CO];

// ---------------------------------------------------------------------------
// Prep A: pack x channel quads: g_x4[b][c4][p] = (x[4c4..4c4+3] at pixel p)
// ---------------------------------------------------------------------------
__global__ void pack_x_kernel(const float* __restrict__ x) {
    int i = blockIdx.x * blockDim.x + threadIdx.x;   // over BI*16*HWI
    if (i < BI*(CI/4)*HWI) {
        int p = i & (HWI-1); int rest = i >> 14;
        int c4 = rest & 15;  int b = rest >> 4;
        const float* src = x + ((size_t)(b*CI + 4*c4))*HWI + p;
        g_x4[i] = make_float4(src[0], src[HWI], src[2*HWI], src[3*HWI]);
    }
}

// ---------------------------------------------------------------------------
// Prep B: transpose w_def [o][c][kk] -> g_wt [kk][c][o]
// ---------------------------------------------------------------------------
__global__ void transpose_wdef_kernel(const float* __restrict__ w_def) {
    int i = blockIdx.x * blockDim.x + threadIdx.x;
    if (i < KKN*CI*CO) {
        int o = i & 63; int rest = i >> 6; int c = rest % CI; int kk = rest / CI;
        g_wt[i] = w_def[(o*CI + c)*KKN + kk];
    }
}

// ---------------------------------------------------------------------------
// Kernel 1: offset conv, 1 pixel/thread, packed f32x2 accumulators.
// Reads channel-quad packed g_x4: 144 LDG.128 per thread.
// ---------------------------------------------------------------------------
__global__ __launch_bounds__(256, 4)
void offset_conv_kernel(const float* __restrict__ w_off,
                        const float* __restrict__ b_off) {
    __shared__ __align__(16) float ws[KKN*CI*JP];
    int tid = threadIdx.x;
    for (int i = tid; i < KKN*CI*JO; i += blockDim.x) {
        int j = i % JO; int rest = i / JO; int c = rest % CI; int tap = rest / CI;
        ws[(tap*CI + c)*JP + j] = w_off[(j*CI + c)*KKN + tap];
    }
    __syncthreads();

    int p = blockIdx.x * blockDim.x + tid;
    int b = p >> 14, rem = p & (HWI-1);
    int h = rem >> 7, w = rem & (WI-1);
    const float4* xb4 = g_x4 + (size_t)b*(CI/4)*HWI;

    u64 acc[9];
    #pragma unroll
    for (int q = 0; q < 9; q++)
        acc[q] = pack2(__ldg(&b_off[2*q]), __ldg(&b_off[2*q+1]));

    for (int tap = 0; tap < KKN; tap++) {
        int ky = tap / 3, kx = tap % 3;
        int y = h - 1 + ky, xx = w - 1 + kx;
        bool v = (y >= 0) & (y < HI) & (xx >= 0) & (xx < WI);
        int idx = y*WI + xx;
        const float* wtap = ws + tap*CI*JP;
        #pragma unroll 2
        for (int c4 = 0; c4 < CI/4; c4++) {
            float4 qv = v ? __ldg(xb4 + (size_t)c4*HWI + idx)
                          : make_float4(0.f, 0.f, 0.f, 0.f);
            const float* qf = (const float*)&qv;
            #pragma unroll
            for (int u = 0; u < 4; u++) {
                u64 a2 = pack2(qf[u], qf[u]);
                const float* wrow = wtap + (4*c4 + u)*JP;
                const ulonglong2* w4 = (const ulonglong2*)wrow;
                #pragma unroll
                for (int q = 0; q < 4; q++) {
                    ulonglong2 wv = w4[q];
                    ffma2(acc[2*q+0], a2, wv.x);
                    ffma2(acc[2*q+1], a2, wv.y);
                }
                u64 w8 = *(const u64*)(wrow + 16);
                ffma2(acc[8], a2, w8);
            }
        }
    }
    #pragma unroll
    for (int q = 0; q < 9; q++) {
        float2 vv = unpack2(acc[q]);
        g_off[(b*JO + 2*q+0)*HWI + rem] = vv.x;
        g_off[(b*JO + 2*q+1)*HWI + rem] = vv.y;
    }
}

// ---------------------------------------------------------------------------
// Kernel 2: WARP-INDEPENDENT per-tap im2col + GEMM.
// Block = 128 threads = one row, but each warp owns 32 px end-to-end with a
// private 8 KB S region. No __syncthreads in the tap loop — only __syncwarp.
// Sampling: lane = own px, channel-quad gathers (LDG.128 from g_x4).
// GEMM: thread tile 8o x 8px within the warp (o0=(lid>>2)*8, px octet 8*(lid&3));
//   weights LDG.128 from g_wt + pack2; next-tap dy/dx prefetched.
// ---------------------------------------------------------------------------
__global__ __launch_bounds__(128, 4)
void deform_main_kernel(float* __restrict__ out) {
    __shared__ __align__(16) float S[4][CI*32];   // per-warp 8 KB, total 32 KB

    int tid = threadIdx.x;
    int wid = tid >> 5, lid = tid & 31;
    int blk = blockIdx.x;
    int b = blk >> 7;
    int h = blk & 127;
    int rowoff = h * WI;
    const float4* x4b = g_x4 + (size_t)b*(CI/4)*HWI;
    int w = wid*32 + lid;                 // own pixel
    const float* offp = g_off + b*JO*HWI + rowoff + w;
    float* Sw = S[wid];

    int o0 = (lid >> 2) * 8;              // 8 output channels
    int pg = lid & 3;                     // px octet base 8*pg within warp

    u64 acc[8][4];
    #pragma unroll
    for (int o = 0; o < 8; o++)
        #pragma unroll
        for (int q = 0; q < 4; q++) acc[o][q] = 0ULL;

    // prefetch tap 0 offsets
    float dy = __ldg(offp + 0*HWI);
    float dx = __ldg(offp + 1*HWI);

    for (int kk = 0; kk < KKN; kk++) {
        __syncwarp();   // warp's previous GEMM done reading Sw

        // bilinear setup for own pixel (dy/dx prefetched)
        float py = (float)(h - 1 + kk / 3) + dy;
        float px = (float)(w - 1 + kk % 3) + dx;
        float y0f = floorf(py), x0f = floorf(px);
        float fy = py - y0f, fx = px - x0f;
        int y0 = (int)y0f, x0 = (int)x0f;
        int y1 = y0 + 1,   x1 = x0 + 1;
        float vy0 = (y0 >= 0 && y0 < HI) ? 1.f : 0.f;
        float vy1 = (y1 >= 0 && y1 < HI) ? 1.f : 0.f;
        float vx0 = (x0 >= 0 && x0 < WI) ? 1.f : 0.f;
        float vx1 = (x1 >= 0 && x1 < WI) ? 1.f : 0.f;
        float w00 = (1.f - fy) * (1.f - fx) * vy0 * vx0;
        float w01 = (1.f - fy) * fx         * vy0 * vx1;
        float w10 = fy         * (1.f - fx) * vy1 * vx0;
        float w11 = fy         * fx         * vy1 * vx1;
        int y0c = min(max(y0, 0), HI-1), y1c = min(max(y1, 0), HI-1);
        int x0c = min(max(x0, 0), WI-1), x1c = min(max(x1, 0), WI-1);
        int i00 = y0c*WI + x0c, i01 = y0c*WI + x1c;
        int i10 = y1c*WI + x0c, i11 = y1c*WI + x1c;

        u64 W00 = pack2(w00, w00), W01 = pack2(w01, w01);
        u64 W10 = pack2(w10, w10), W11 = pack2(w11, w11);

        // sample channel quads -> Sw[4c4+k][lid]
        #pragma unroll 2
        for (int c4 = 0; c4 < CI/4; c4++) {
            const float4* xp = x4b + (size_t)c4*HWI;
            ulonglong2 n00 = __ldg((const ulonglong2*)(xp + i00));
            ulonglong2 n01 = __ldg((const ulonglong2*)(xp + i01));
            ulonglong2 n10 = __ldg((const ulonglong2*)(xp + i10));
            ulonglong2 n11 = __ldg((const ulonglong2*)(xp + i11));
            u64 sLo = 0ULL, sHi = 0ULL;
            ffma2(sLo, W00, n00.x);  ffma2(sHi, W00, n00.y);
            ffma2(sLo, W01, n01.x);  ffma2(sHi, W01, n01.y);
            ffma2(sLo, W10, n10.x);  ffma2(sHi, W10, n10.y);
            ffma2(sLo, W11, n11.x);  ffma2(sHi, W11, n11.y);
            float2 a = unpack2(sLo), c = unpack2(sHi);
            Sw[(4*c4+0)*32 + lid] = a.x;
            Sw[(4*c4+1)*32 + lid] = a.y;
            Sw[(4*c4+2)*32 + lid] = c.x;
            Sw[(4*c4+3)*32 + lid] = c.y;
        }
        __syncwarp();

        // prefetch next tap's offsets (hidden under GEMM)
        if (kk + 1 < KKN) {
            dy = __ldg(offp + (2*kk + 2)*HWI);
            dx = __ldg(offp + (2*kk + 3)*HWI);
        }

        // GEMM: acc[8o][8px] += W[o][c] * Sw[c][px]
        const float* wk = g_wt + kk*CI*CO + o0;
        #pragma unroll 2
        for (int c = 0; c < CI; c++) {
            const float* wr = wk + (c << 6);
            float4 wa = __ldg((const float4*)(wr));
            float4 wb = __ldg((const float4*)(wr + 4));
            u64 w2[8];
            w2[0] = pack2(wa.x, wa.x); w2[1] = pack2(wa.y, wa.y);
            w2[2] = pack2(wa.z, wa.z); w2[3] = pack2(wa.w, wa.w);
            w2[4] = pack2(wb.x, wb.x); w2[5] = pack2(wb.y, wb.y);
            w2[6] = pack2(wb.z, wb.z); w2[7] = pack2(wb.w, wb.w);
            const float* srow = Sw + c*32 + 8*pg;
            ulonglong2 sj0 = *(const ulonglong2*)(srow);
            ulonglong2 sj1 = *(const ulonglong2*)(srow + 4);
            #pragma unroll
            for (int o = 0; o < 8; o++) {
                ffma2(acc[o][0], sj0.x, w2[o]);
                ffma2(acc[o][1], sj0.y, w2[o]);
                ffma2(acc[o][2], sj1.x, w2[o]);
                ffma2(acc[o][3], sj1.y, w2[o]);
            }
        }
    }

    // write out: thread's px octet at wid*32 + 8*pg
    #pragma unroll
    for (int o = 0; o < 8; o++) {
        float* orow = out + (b*CO + o0 + o)*HWI + rowoff + wid*32 + 8*pg;
        float2 v0 = unpack2(acc[o][0]);
        float2 v1 = unpack2(acc[o][1]);
        float2 v2 = unpack2(acc[o][2]);
        float2 v3 = unpack2(acc[o][3]);
        *(float4*)(orow)     = make_float4(v0.x, v0.y, v1.x, v1.y);
        *(float4*)(orow + 4) = make_float4(v2.x, v2.y, v3.x, v3.y);
    }
}

// ---------------------------------------------------------------------------
// Launch
// Inputs: x (4*64*128*128), w_off (18*64*9), b_off (18), w_def (64*64*9)
// Output: (4, 64, 128, 128) fp32
// ---------------------------------------------------------------------------
extern "C" void kernel_launch(void* const* d_in, const int* in_sizes, int n_in,
                              void* d_out, int out_size) {
    const float* x     = (const float*)d_in[0];
    const float* w_off = (const float*)d_in[1];
    const float* b_off = (const float*)d_in[2];
    const float* w_def = (const float*)d_in[3];
    float* out = (float*)d_out;

    const int total_px = BI*HWI;  // 65536

    pack_x_kernel<<<(BI*(CI/4)*HWI + 255)/256, 256>>>(x);
    transpose_wdef_kernel<<<(KKN*CI*CO + 255)/256, 256>>>(w_def);
    offset_conv_kernel<<<total_px/256, 256>>>(w_off, b_off);
    deform_main_kernel<<<total_px/TPX, TPX>>>(out);
}